// round 1
// baseline (speedup 1.0000x reference)
#include <cuda_runtime.h>
#include <cuda_bf16.h>

// MeshNN: u(x) = sum_i hat_i(x) * W_i on a uniform 512-node grid.
// Only the two hats covering x's segment are nonzero -> O(1) per point.
// W = [w_dd[0], w_uu[0..509], w_dd[1]]. Boundary hats use ghost nodes
// (c0 - L/1000) and (cL + L/1000), exactly like the reference.

#define NP_NODES 512

__global__ __launch_bounds__(256) void meshnn_kernel(
    const float4* __restrict__ x4,
    const float*  __restrict__ coords,
    const float*  __restrict__ w_uu,
    const float*  __restrict__ w_dd,
    float4*       __restrict__ out4,
    int n4)
{
    __shared__ float csh[NP_NODES];
    __shared__ float wsh[NP_NODES];

    // Stage coords and fused weight vector into shared (4 KB total).
    for (int i = threadIdx.x; i < NP_NODES; i += blockDim.x) {
        csh[i] = coords[i];
        float w;
        if (i == 0)                 w = w_dd[0];
        else if (i == NP_NODES - 1) w = w_dd[1];
        else                        w = w_uu[i - 1];
        wsh[i] = w;
    }
    __syncthreads();

    const float c0    = csh[0];
    const float cL    = csh[NP_NODES - 1];
    const float Ldom  = cL - c0;
    const float ghost = Ldom * 0.001f;
    const float inv_h = (float)(NP_NODES - 1) / Ldom;

    int gid = blockIdx.x * blockDim.x + threadIdx.x;
    if (gid >= n4) return;

    float4 xin = x4[gid];
    float xs[4] = {xin.x, xin.y, xin.z, xin.w};
    float rs[4];

#pragma unroll
    for (int k = 0; k < 4; k++) {
        float xf = xs[k];

        // Segment index from the uniform-grid formula, refined against the
        // actual fp32 coords so x lies in [csh[j], csh[j+1]).
        int j = (int)((xf - c0) * inv_h);
        j = min(max(j, 0), NP_NODES - 2);
        if (xf < csh[j] && j > 0)                       j--;
        else if (j < NP_NODES - 2 && xf >= csh[j + 1])  j++;

        const float cjm = (j == 0)              ? (c0 - ghost) : csh[j - 1];
        const float cj  = csh[j];
        const float cj1 = csh[j + 1];
        const float cj2 = (j + 1 == NP_NODES-1) ? (cL + ghost) : csh[j + 2];

        // hat_j(x): support [cjm, cj1], peak at cj
        float l0 = fmaxf(1.0f - fmaxf(cj  - xf, 0.0f) / (cj  - cjm), 0.0f);
        float r0 = fmaxf(1.0f - fmaxf(xf  - cj, 0.0f) / (cj1 - cj ), 0.0f);
        float h0 = l0 + r0 - 1.0f;

        // hat_{j+1}(x): support [cj, cj2], peak at cj1
        float l1 = fmaxf(1.0f - fmaxf(cj1 - xf,  0.0f) / (cj1 - cj ), 0.0f);
        float r1 = fmaxf(1.0f - fmaxf(xf  - cj1, 0.0f) / (cj2 - cj1), 0.0f);
        float h1 = l1 + r1 - 1.0f;

        rs[k] = h0 * wsh[j] + h1 * wsh[j + 1];
    }

    out4[gid] = make_float4(rs[0], rs[1], rs[2], rs[3]);
}

extern "C" void kernel_launch(void* const* d_in, const int* in_sizes, int n_in,
                              void* d_out, int out_size)
{
    const float* x      = (const float*)d_in[0];
    const float* coords = (const float*)d_in[1];
    const float* w_uu   = (const float*)d_in[2];
    const float* w_dd   = (const float*)d_in[3];
    float* out = (float*)d_out;

    int n  = in_sizes[0];   // 262144 (x is (N,1))
    int n4 = n >> 2;        // N is divisible by 4

    int threads = 256;
    int blocks  = (n4 + threads - 1) / threads;
    meshnn_kernel<<<blocks, threads>>>(
        (const float4*)x, coords, w_uu, w_dd, (float4*)out, n4);
}

// round 2
// speedup vs baseline: 1.0295x; 1.0295x over previous
#include <cuda_runtime.h>
#include <cuda_bf16.h>

// MeshNN: u(x) = sum_i hat_i(x) * W_i on a uniform 512-node grid.
// Only the two hats covering x's segment are nonzero -> O(1) per point.
// Scalar version: 1 point/thread -> 262144 threads -> ~56 warps/SM, which
// hides the DRAM load latency that bounded the float4 version (occ was 20%).
// coords (2KB) + weights are read via __ldg and live in L1 after wave 1;
// no smem staging, no __syncthreads.

#define NP_NODES 512

__global__ __launch_bounds__(256) void meshnn_kernel(
    const float* __restrict__ x,
    const float* __restrict__ coords,
    const float* __restrict__ w_uu,
    const float* __restrict__ w_dd,
    float*       __restrict__ out,
    int n)
{
    int gid = blockIdx.x * blockDim.x + threadIdx.x;
    if (gid >= n) return;

    float xf = __ldg(&x[gid]);   // issue the DRAM load first

    const float c0    = __ldg(&coords[0]);
    const float cL    = __ldg(&coords[NP_NODES - 1]);
    const float Ldom  = cL - c0;
    const float ghost = Ldom * 0.001f;
    const float inv_h = (float)(NP_NODES - 1) / Ldom;

    // Segment index from the uniform-grid formula, refined against the
    // actual fp32 coords so x lies in [coords[j], coords[j+1]).
    int j = (int)((xf - c0) * inv_h);
    j = min(max(j, 0), NP_NODES - 2);
    float cj  = __ldg(&coords[j]);
    float cj1 = __ldg(&coords[j + 1]);
    if (xf < cj && j > 0)                      { j--; cj1 = cj;  cj = __ldg(&coords[j]); }
    else if (j < NP_NODES - 2 && xf >= cj1)    { j++; cj  = cj1; cj1 = __ldg(&coords[j + 1]); }

    const float cjm = (j == 0)                ? (c0 - ghost) : __ldg(&coords[j - 1]);
    const float cj2 = (j + 1 == NP_NODES - 1) ? (cL + ghost) : __ldg(&coords[j + 2]);

    // hat_j(x): support [cjm, cj1], peak at cj
    float l0 = fmaxf(1.0f - fmaxf(cj  - xf, 0.0f) / (cj  - cjm), 0.0f);
    float r0 = fmaxf(1.0f - fmaxf(xf  - cj, 0.0f) / (cj1 - cj ), 0.0f);
    float h0 = l0 + r0 - 1.0f;

    // hat_{j+1}(x): support [cj, cj2], peak at cj1
    float l1 = fmaxf(1.0f - fmaxf(cj1 - xf,  0.0f) / (cj1 - cj ), 0.0f);
    float r1 = fmaxf(1.0f - fmaxf(xf  - cj1, 0.0f) / (cj2 - cj1), 0.0f);
    float h1 = l1 + r1 - 1.0f;

    // Fused weight vector W = [w_dd[0], w_uu[0..509], w_dd[1]]
    float wj  = (j == 0)                ? __ldg(&w_dd[0]) : __ldg(&w_uu[j - 1]);
    float wj1 = (j + 1 == NP_NODES - 1) ? __ldg(&w_dd[1]) : __ldg(&w_uu[j]);

    out[gid] = h0 * wj + h1 * wj1;
}

extern "C" void kernel_launch(void* const* d_in, const int* in_sizes, int n_in,
                              void* d_out, int out_size)
{
    const float* x      = (const float*)d_in[0];
    const float* coords = (const float*)d_in[1];
    const float* w_uu   = (const float*)d_in[2];
    const float* w_dd   = (const float*)d_in[3];
    float* out = (float*)d_out;

    int n = in_sizes[0];   // 262144
    int threads = 256;
    int blocks  = (n + threads - 1) / threads;   // 1024
    meshnn_kernel<<<blocks, threads>>>(x, coords, w_uu, w_dd, out, n);
}

// round 3
// speedup vs baseline: 1.3478x; 1.3092x over previous
#include <cuda_runtime.h>
#include <cuda_bf16.h>

// MeshNN: u(x) = sum_i hat_i(x) * W_i, uniform 512-node grid, W = [w_dd0, w_uu..., w_dd1].
// For x in segment [c_j, c_{j+1}] the reference's hat formula collapses EXACTLY to
// linear interpolation:  u = W[j] + t * (W[j+1] - W[j]),  t = (x - c_j)/(c_{j+1} - c_j).
// (Ghost-node boundary hats reduce to the same expression inside the domain;
//  all non-neighbor hats are identically zero.)  One divide, one FMA per point.

#define NP_NODES 512

__global__ __launch_bounds__(256) void meshnn_kernel(
    const float* __restrict__ x,
    const float* __restrict__ coords,
    const float* __restrict__ w_uu,
    const float* __restrict__ w_dd,
    float*       __restrict__ out,
    int n)
{
    int gid = blockIdx.x * blockDim.x + threadIdx.x;
    if (gid >= n) return;

    float xf = __ldg(&x[gid]);   // DRAM load first

    const float c0    = __ldg(&coords[0]);              // broadcast L1 hits
    const float cL    = __ldg(&coords[NP_NODES - 1]);
    const float inv_h = (float)(NP_NODES - 1) / (cL - c0);

    // Segment index from the uniform-grid formula, refined against the actual
    // fp32 coords so xf lies in [coords[j], coords[j+1]).
    int j = (int)((xf - c0) * inv_h);
    j = min(max(j, 0), NP_NODES - 2);
    float cj  = __ldg(&coords[j]);
    float cj1 = __ldg(&coords[j + 1]);
    if (xf < cj && j > 0)                     { j--; cj1 = cj;  cj  = __ldg(&coords[j]); }
    else if (xf >= cj1 && j < NP_NODES - 2)   { j++; cj  = cj1; cj1 = __ldg(&coords[j + 1]); }

    float t = __fdividef(xf - cj, cj1 - cj);

    // Fused weight vector W = [w_dd[0], w_uu[0..509], w_dd[1]]
    float wj  = (j == 0)            ? __ldg(&w_dd[0]) : __ldg(&w_uu[j - 1]);
    float wj1 = (j == NP_NODES - 2) ? __ldg(&w_dd[1]) : __ldg(&w_uu[j]);

    out[gid] = fmaf(t, wj1 - wj, wj);
}

extern "C" void kernel_launch(void* const* d_in, const int* in_sizes, int n_in,
                              void* d_out, int out_size)
{
    const float* x      = (const float*)d_in[0];
    const float* coords = (const float*)d_in[1];
    const float* w_uu   = (const float*)d_in[2];
    const float* w_dd   = (const float*)d_in[3];
    float* out = (float*)d_out;

    int n = in_sizes[0];   // 262144
    int threads = 256;
    int blocks  = (n + threads - 1) / threads;   // 1024
    meshnn_kernel<<<blocks, threads>>>(x, coords, w_uu, w_dd, out, n);
}